// round 5
// baseline (speedup 1.0000x reference)
#include <cuda_runtime.h>

// VQCodebook: nearest-code argmin + gather + loss.
// Exact-rounding replication of:
//   d = sum(z^2,-1,keepdims) + sum(c^2,1) - 2*einsum('btd,kd->btk')
//   idx = argmin(d, -1) (first-index tie-break)
//   z_q_st = z + (codebook[idx] - z)   (fp32 rounded ops)
//   loss = 2 * mean((z_q - z)^2)
//
// Output layout (f32): [z_q_st (65536*64)] [indices (65536)] [loss (1)]

typedef unsigned long long ull;

#define N_TOK   65536
#define DIM     64
#define NCODE   1024
#define CHUNK   64
#define BT      128            // threads per block
#define TPB     (BT * 2)       // tokens per block (2 per thread, packed f32x2)
#define OUT_IDX  (N_TOK * DIM)           // 4194304
#define OUT_LOSS (OUT_IDX + N_TOK)       // 4259840

__device__ float  g_s2[NCODE];
__device__ double g_lacc;

__device__ __forceinline__ ull pack2(float a, float b) {
    ull r;
    asm("mov.b64 %0, {%1, %2};" : "=l"(r) : "f"(a), "f"(b));
    return r;
}
__device__ __forceinline__ void unpack2(ull v, float& a, float& b) {
    asm("mov.b64 {%0, %1}, %2;" : "=f"(a), "=f"(b) : "l"(v));
}
// Packed dual fp32 FMA; each lane rounds exactly like scalar fma.rn.f32.
__device__ __forceinline__ ull fma2(ull a, ull b, ull c) {
    ull r;
    asm("fma.rn.f32x2 %0, %1, %2, %3;" : "=l"(r) : "l"(a), "l"(b), "l"(c));
    return r;
}

// ---------------------------------------------------------------------------
// Kernel 0: per-code squared norms (sequential fp32 left-fold, matching
// jnp.sum(codebook**2, axis=1) to within << ulp(d)) + zero the loss accumulator.
// ---------------------------------------------------------------------------
__global__ void k_init(const float* __restrict__ cb) {
    int k = blockIdx.x * blockDim.x + threadIdx.x;
    if (k == 0) g_lacc = 0.0;
    if (k < NCODE) {
        const float* r = cb + (size_t)k * DIM;
        float s = 0.0f;
#pragma unroll
        for (int d = 0; d < DIM; ++d)
            s = __fadd_rn(s, __fmul_rn(r[d], r[d]));
        g_s2[k] = s;
    }
}

// ---------------------------------------------------------------------------
// Kernel 1: main. Each thread owns 2 tokens packed into f32x2 lanes.
// Codebook staged in smem pre-splatted as (c,c) pairs; inner loop is
// 2x LDS.128 + 4x FFMA2 per dim -> FFMA-pipe bound.
// ---------------------------------------------------------------------------
__global__ void __launch_bounds__(BT) k_main(const float* __restrict__ z,
                                             const float* __restrict__ cb,
                                             float* __restrict__ out) {
    __shared__ __align__(16) ull ct2[DIM][CHUNK + 2];  // [d][k] splatted pairs
    __shared__ float  s2s[CHUNK];
    __shared__ double lred[BT];

    const int tid = threadIdx.x;
    const int t0  = blockIdx.x * TPB + tid;
    const int t1  = t0 + BT;

    // Load z rows for both tokens; pack lanes; sequential-left-fold s1 per token.
    ull   zp[DIM];
    float s1a = 0.0f, s1b = 0.0f;
    {
        const float4* r0 = reinterpret_cast<const float4*>(z + (size_t)t0 * DIM);
        const float4* r1 = reinterpret_cast<const float4*>(z + (size_t)t1 * DIM);
#pragma unroll
        for (int q = 0; q < DIM / 4; ++q) {
            float4 a = r0[q];
            float4 b = r1[q];
            zp[4 * q + 0] = pack2(a.x, b.x);
            zp[4 * q + 1] = pack2(a.y, b.y);
            zp[4 * q + 2] = pack2(a.z, b.z);
            zp[4 * q + 3] = pack2(a.w, b.w);
            s1a = __fadd_rn(s1a, __fmul_rn(a.x, a.x));
            s1a = __fadd_rn(s1a, __fmul_rn(a.y, a.y));
            s1a = __fadd_rn(s1a, __fmul_rn(a.z, a.z));
            s1a = __fadd_rn(s1a, __fmul_rn(a.w, a.w));
            s1b = __fadd_rn(s1b, __fmul_rn(b.x, b.x));
            s1b = __fadd_rn(s1b, __fmul_rn(b.y, b.y));
            s1b = __fadd_rn(s1b, __fmul_rn(b.z, b.z));
            s1b = __fadd_rn(s1b, __fmul_rn(b.w, b.w));
        }
    }

    float best0 = 3.402823466e38f, best1 = 3.402823466e38f;
    int   bi0 = 0, bi1 = 0;

    for (int c0 = 0; c0 < NCODE; c0 += CHUNK) {
        __syncthreads();
        // Stage chunk: coalesced global read, splat into [d][k] pairs.
#pragma unroll
        for (int r = 0; r < (CHUNK * DIM) / BT; ++r) {
            int   i = tid + r * BT;
            int   k = i >> 6;      // code within chunk
            int   d = i & 63;      // dim
            float v = cb[(size_t)(c0 + k) * DIM + d];
            ct2[d][k] = pack2(v, v);
        }
        if (tid < CHUNK) s2s[tid] = g_s2[c0 + tid];
        __syncthreads();

        // Process 4 codes at a time: 4 independent f32x2 FMA chains (ILP=4).
#pragma unroll 1
        for (int cg = 0; cg < CHUNK; cg += 4) {
            ull a0 = 0ull, a1 = 0ull, a2 = 0ull, a3 = 0ull;
#pragma unroll
            for (int d = 0; d < DIM; ++d) {
                ulonglong2 p0 = *reinterpret_cast<const ulonglong2*>(&ct2[d][cg]);
                ulonglong2 p1 = *reinterpret_cast<const ulonglong2*>(&ct2[d][cg + 2]);
                a0 = fma2(zp[d], p0.x, a0);
                a1 = fma2(zp[d], p0.y, a1);
                a2 = fma2(zp[d], p1.x, a2);
                a3 = fma2(zp[d], p1.y, a3);
            }
            const int kb = c0 + cg;
            // d_k = fl( fl(s1 + s2_k) - fl(2*e_k) ); 2*e is exact in fp32.
            // Strict '<' with ascending k == jnp.argmin first-index tie-break.
            auto upd = [&](ull acc, int kk) {
                float e0, e1;
                unpack2(acc, e0, e1);
                float s2v = s2s[kk - c0];
                float d0  = __fsub_rn(__fadd_rn(s1a, s2v), __fmul_rn(2.0f, e0));
                float d1  = __fsub_rn(__fadd_rn(s1b, s2v), __fmul_rn(2.0f, e1));
                if (d0 < best0) { best0 = d0; bi0 = kk; }
                if (d1 < best1) { best1 = d1; bi1 = kk; }
            };
            upd(a0, kb + 0);
            upd(a1, kb + 1);
            upd(a2, kb + 2);
            upd(a3, kb + 3);
        }
    }

    // Epilogue: gather code rows, write z_q_st = fl(z + fl(zq - z)),
    // accumulate loss partial in double.
    double lsum = 0.0;
    {
        const float4* cr = reinterpret_cast<const float4*>(cb + (size_t)bi0 * DIM);
        float4* orow = reinterpret_cast<float4*>(out + (size_t)t0 * DIM);
#pragma unroll
        for (int q = 0; q < DIM / 4; ++q) {
            float4 cv = cr[q];
            float4 w;
            float za, zb, df;
            unpack2(zp[4 * q + 0], za, zb);
            df = __fsub_rn(cv.x, za); w.x = __fadd_rn(za, df); lsum += (double)__fmul_rn(df, df);
            unpack2(zp[4 * q + 1], za, zb);
            df = __fsub_rn(cv.y, za); w.y = __fadd_rn(za, df); lsum += (double)__fmul_rn(df, df);
            unpack2(zp[4 * q + 2], za, zb);
            df = __fsub_rn(cv.z, za); w.z = __fadd_rn(za, df); lsum += (double)__fmul_rn(df, df);
            unpack2(zp[4 * q + 3], za, zb);
            df = __fsub_rn(cv.w, za); w.w = __fadd_rn(za, df); lsum += (double)__fmul_rn(df, df);
            orow[q] = w;
        }
    }
    {
        const float4* cr = reinterpret_cast<const float4*>(cb + (size_t)bi1 * DIM);
        float4* orow = reinterpret_cast<float4*>(out + (size_t)t1 * DIM);
#pragma unroll
        for (int q = 0; q < DIM / 4; ++q) {
            float4 cv = cr[q];
            float4 w;
            float za, zb, df;
            unpack2(zp[4 * q + 0], za, zb);
            df = __fsub_rn(cv.x, zb); w.x = __fadd_rn(zb, df); lsum += (double)__fmul_rn(df, df);
            unpack2(zp[4 * q + 1], za, zb);
            df = __fsub_rn(cv.y, zb); w.y = __fadd_rn(zb, df); lsum += (double)__fmul_rn(df, df);
            unpack2(zp[4 * q + 2], za, zb);
            df = __fsub_rn(cv.z, zb); w.z = __fadd_rn(zb, df); lsum += (double)__fmul_rn(df, df);
            unpack2(zp[4 * q + 3], za, zb);
            df = __fsub_rn(cv.w, zb); w.w = __fadd_rn(zb, df); lsum += (double)__fmul_rn(df, df);
            orow[q] = w;
        }
    }

    out[OUT_IDX + t0] = (float)bi0;
    out[OUT_IDX + t1] = (float)bi1;

    // Block-reduce loss partials, one atomicAdd(double) per block.
    lred[tid] = lsum;
    __syncthreads();
#pragma unroll
    for (int s = BT / 2; s > 0; s >>= 1) {
        if (tid < s) lred[tid] += lred[tid + s];
        __syncthreads();
    }
    if (tid == 0) atomicAdd(&g_lacc, lred[0]);
}

// ---------------------------------------------------------------------------
// Kernel 2: finalize loss = fl(m + m), m = mean((zq - z)^2).
// ---------------------------------------------------------------------------
__global__ void k_fin(float* __restrict__ out) {
    double m  = g_lacc / (double)((double)N_TOK * (double)DIM);
    float  mf = (float)m;
    out[OUT_LOSS] = __fadd_rn(mf, mf);
}

extern "C" void kernel_launch(void* const* d_in, const int* in_sizes, int n_in,
                              void* d_out, int out_size) {
    const float* z  = (const float*)d_in[0];   // [8,8192,64] f32
    const float* cb = (const float*)d_in[1];   // [1024,64]  f32
    float* out = (float*)d_out;

    k_init<<<(NCODE + 127) / 128, 128>>>(cb);
    k_main<<<N_TOK / TPB, BT>>>(z, cb, out);
    k_fin<<<1, 1>>>(out);
}

// round 6
// speedup vs baseline: 1.0036x; 1.0036x over previous
#include <cuda_runtime.h>

// VQCodebook: nearest-code argmin + gather + loss.
// Exact-rounding replication of:
//   d = sum(z^2,-1,keepdims) + sum(c^2,1) - 2*einsum('btd,kd->btk')
//   idx = argmin(d, -1) (first-index tie-break)
//   z_q_st = z + (codebook[idx] - z)   (fp32 rounded ops)
//   loss = 2 * mean((z_q - z)^2)
//
// Output layout (f32): [z_q_st (65536*64)] [indices (65536)] [loss (1)]

typedef unsigned long long ull;

#define N_TOK   65536
#define DIM     64
#define NCODE   1024
#define CHUNK   64
#define BT      128            // threads per block
#define TPB     (BT * 2)       // tokens per block (2 per thread, packed f32x2)
#define OUT_IDX  (N_TOK * DIM)           // 4194304
#define OUT_LOSS (OUT_IDX + N_TOK)       // 4259840

__device__ float  g_s2[NCODE];
__device__ double g_lacc;

__device__ __forceinline__ ull pack2(float a, float b) {
    ull r;
    asm("mov.b64 %0, {%1, %2};" : "=l"(r) : "f"(a), "f"(b));
    return r;
}
__device__ __forceinline__ void unpack2(ull v, float& a, float& b) {
    asm("mov.b64 {%0, %1}, %2;" : "=f"(a), "=f"(b) : "l"(v));
}
// Packed dual fp32 FMA; each lane rounds exactly like scalar fma.rn.f32.
__device__ __forceinline__ ull fma2(ull a, ull b, ull c) {
    ull r;
    asm("fma.rn.f32x2 %0, %1, %2, %3;" : "=l"(r) : "l"(a), "l"(b), "l"(c));
    return r;
}

// ---------------------------------------------------------------------------
// Kernel 0: per-code squared norms (sequential fp32 left-fold, matching
// jnp.sum(codebook**2, axis=1) to within << ulp(d)) + zero the loss accumulator.
// ---------------------------------------------------------------------------
__global__ void k_init(const float* __restrict__ cb) {
    int k = blockIdx.x * blockDim.x + threadIdx.x;
    if (k == 0) g_lacc = 0.0;
    if (k < NCODE) {
        const float* r = cb + (size_t)k * DIM;
        float s = 0.0f;
#pragma unroll
        for (int d = 0; d < DIM; ++d)
            s = __fadd_rn(s, __fmul_rn(r[d], r[d]));
        g_s2[k] = s;
    }
}

// ---------------------------------------------------------------------------
// Kernel 1: main. Each thread owns 2 tokens packed into f32x2 lanes.
// Codebook staged in smem pre-splatted as (c,c) pairs; inner loop is
// 2x LDS.128 + 4x FFMA2 per dim -> FFMA-pipe bound.
// ---------------------------------------------------------------------------
__global__ void __launch_bounds__(BT) k_main(const float* __restrict__ z,
                                             const float* __restrict__ cb,
                                             float* __restrict__ out) {
    __shared__ __align__(16) ull ct2[DIM][CHUNK + 2];  // [d][k] splatted pairs
    __shared__ float  s2s[CHUNK];
    __shared__ double lred[BT];

    const int tid = threadIdx.x;
    const int t0  = blockIdx.x * TPB + tid;
    const int t1  = t0 + BT;

    // Load z rows for both tokens; pack lanes; sequential-left-fold s1 per token.
    ull   zp[DIM];
    float s1a = 0.0f, s1b = 0.0f;
    {
        const float4* r0 = reinterpret_cast<const float4*>(z + (size_t)t0 * DIM);
        const float4* r1 = reinterpret_cast<const float4*>(z + (size_t)t1 * DIM);
#pragma unroll
        for (int q = 0; q < DIM / 4; ++q) {
            float4 a = r0[q];
            float4 b = r1[q];
            zp[4 * q + 0] = pack2(a.x, b.x);
            zp[4 * q + 1] = pack2(a.y, b.y);
            zp[4 * q + 2] = pack2(a.z, b.z);
            zp[4 * q + 3] = pack2(a.w, b.w);
            s1a = __fadd_rn(s1a, __fmul_rn(a.x, a.x));
            s1a = __fadd_rn(s1a, __fmul_rn(a.y, a.y));
            s1a = __fadd_rn(s1a, __fmul_rn(a.z, a.z));
            s1a = __fadd_rn(s1a, __fmul_rn(a.w, a.w));
            s1b = __fadd_rn(s1b, __fmul_rn(b.x, b.x));
            s1b = __fadd_rn(s1b, __fmul_rn(b.y, b.y));
            s1b = __fadd_rn(s1b, __fmul_rn(b.z, b.z));
            s1b = __fadd_rn(s1b, __fmul_rn(b.w, b.w));
        }
    }

    float best0 = 3.402823466e38f, best1 = 3.402823466e38f;
    int   bi0 = 0, bi1 = 0;

    for (int c0 = 0; c0 < NCODE; c0 += CHUNK) {
        __syncthreads();
        // Stage chunk: coalesced global read, splat into [d][k] pairs.
#pragma unroll
        for (int r = 0; r < (CHUNK * DIM) / BT; ++r) {
            int   i = tid + r * BT;
            int   k = i >> 6;      // code within chunk
            int   d = i & 63;      // dim
            float v = cb[(size_t)(c0 + k) * DIM + d];
            ct2[d][k] = pack2(v, v);
        }
        if (tid < CHUNK) s2s[tid] = g_s2[c0 + tid];
        __syncthreads();

        // Process 4 codes at a time: 4 independent f32x2 FMA chains (ILP=4).
#pragma unroll 1
        for (int cg = 0; cg < CHUNK; cg += 4) {
            ull a0 = 0ull, a1 = 0ull, a2 = 0ull, a3 = 0ull;
#pragma unroll
            for (int d = 0; d < DIM; ++d) {
                ulonglong2 p0 = *reinterpret_cast<const ulonglong2*>(&ct2[d][cg]);
                ulonglong2 p1 = *reinterpret_cast<const ulonglong2*>(&ct2[d][cg + 2]);
                a0 = fma2(zp[d], p0.x, a0);
                a1 = fma2(zp[d], p0.y, a1);
                a2 = fma2(zp[d], p1.x, a2);
                a3 = fma2(zp[d], p1.y, a3);
            }
            const int kb = c0 + cg;
            // d_k = fl( fl(s1 + s2_k) - fl(2*e_k) ); 2*e is exact in fp32.
            // Strict '<' with ascending k == jnp.argmin first-index tie-break.
            auto upd = [&](ull acc, int kk) {
                float e0, e1;
                unpack2(acc, e0, e1);
                float s2v = s2s[kk - c0];
                float d0  = __fsub_rn(__fadd_rn(s1a, s2v), __fmul_rn(2.0f, e0));
                float d1  = __fsub_rn(__fadd_rn(s1b, s2v), __fmul_rn(2.0f, e1));
                if (d0 < best0) { best0 = d0; bi0 = kk; }
                if (d1 < best1) { best1 = d1; bi1 = kk; }
            };
            upd(a0, kb + 0);
            upd(a1, kb + 1);
            upd(a2, kb + 2);
            upd(a3, kb + 3);
        }
    }

    // Epilogue: gather code rows, write z_q_st = fl(z + fl(zq - z)),
    // accumulate loss partial in double.
    double lsum = 0.0;
    {
        const float4* cr = reinterpret_cast<const float4*>(cb + (size_t)bi0 * DIM);
        float4* orow = reinterpret_cast<float4*>(out + (size_t)t0 * DIM);
#pragma unroll
        for (int q = 0; q < DIM / 4; ++q) {
            float4 cv = cr[q];
            float4 w;
            float za, zb, df;
            unpack2(zp[4 * q + 0], za, zb);
            df = __fsub_rn(cv.x, za); w.x = __fadd_rn(za, df); lsum += (double)__fmul_rn(df, df);
            unpack2(zp[4 * q + 1], za, zb);
            df = __fsub_rn(cv.y, za); w.y = __fadd_rn(za, df); lsum += (double)__fmul_rn(df, df);
            unpack2(zp[4 * q + 2], za, zb);
            df = __fsub_rn(cv.z, za); w.z = __fadd_rn(za, df); lsum += (double)__fmul_rn(df, df);
            unpack2(zp[4 * q + 3], za, zb);
            df = __fsub_rn(cv.w, za); w.w = __fadd_rn(za, df); lsum += (double)__fmul_rn(df, df);
            orow[q] = w;
        }
    }
    {
        const float4* cr = reinterpret_cast<const float4*>(cb + (size_t)bi1 * DIM);
        float4* orow = reinterpret_cast<float4*>(out + (size_t)t1 * DIM);
#pragma unroll
        for (int q = 0; q < DIM / 4; ++q) {
            float4 cv = cr[q];
            float4 w;
            float za, zb, df;
            unpack2(zp[4 * q + 0], za, zb);
            df = __fsub_rn(cv.x, zb); w.x = __fadd_rn(zb, df); lsum += (double)__fmul_rn(df, df);
            unpack2(zp[4 * q + 1], za, zb);
            df = __fsub_rn(cv.y, zb); w.y = __fadd_rn(zb, df); lsum += (double)__fmul_rn(df, df);
            unpack2(zp[4 * q + 2], za, zb);
            df = __fsub_rn(cv.z, zb); w.z = __fadd_rn(zb, df); lsum += (double)__fmul_rn(df, df);
            unpack2(zp[4 * q + 3], za, zb);
            df = __fsub_rn(cv.w, zb); w.w = __fadd_rn(zb, df); lsum += (double)__fmul_rn(df, df);
            orow[q] = w;
        }
    }

    out[OUT_IDX + t0] = (float)bi0;
    out[OUT_IDX + t1] = (float)bi1;

    // Block-reduce loss partials, one atomicAdd(double) per block.
    lred[tid] = lsum;
    __syncthreads();
#pragma unroll
    for (int s = BT / 2; s > 0; s >>= 1) {
        if (tid < s) lred[tid] += lred[tid + s];
        __syncthreads();
    }
    if (tid == 0) atomicAdd(&g_lacc, lred[0]);
}

// ---------------------------------------------------------------------------
// Kernel 2: finalize loss = fl(m + m), m = mean((zq - z)^2).
// ---------------------------------------------------------------------------
__global__ void k_fin(float* __restrict__ out) {
    double m  = g_lacc / (double)((double)N_TOK * (double)DIM);
    float  mf = (float)m;
    out[OUT_LOSS] = __fadd_rn(mf, mf);
}

extern "C" void kernel_launch(void* const* d_in, const int* in_sizes, int n_in,
                              void* d_out, int out_size) {
    const float* z  = (const float*)d_in[0];   // [8,8192,64] f32
    const float* cb = (const float*)d_in[1];   // [1024,64]  f32
    float* out = (float*)d_out;

    k_init<<<(NCODE + 127) / 128, 128>>>(cb);
    k_main<<<N_TOK / TPB, BT>>>(z, cb, out);
    k_fin<<<1, 1>>>(out);
}

// round 8
// speedup vs baseline: 1.1751x; 1.1708x over previous
#include <cuda_runtime.h>
#include <cuda_bf16.h>
#include <cstdint>

// VQCodebook: mma.sync (HMMA) bf16 hi/lo-split distances + exact fp32 rescue.
// Out (f32): [z_q_st 65536*64][indices 65536][loss 1]

#define N_TOK   65536
#define DIM     64
#define NCODE   1024
#define OUT_IDX (N_TOK * DIM)
#define OUT_LOSS (OUT_IDX + N_TOK)
#define THRESH  1e-4f

// smem layout (bytes)
#define SM_BF0   0          // chunk buf0: 2048 uint4 = 32768
#define SM_BF1   32768      // chunk buf1
#define SM_S2    65536      // 1024 f32
#define SM_S1    69632      // 128 f32
#define SM_TOTAL 70144

__device__ float  g_s2[NCODE];
__device__ uint4  g_bfrag[8 * 2048];   // [chunk][group][ks][lane] = {bh0,bh1,bl0,bl1}
__device__ int    g_idx[N_TOK];
__device__ int    g_list[N_TOK];
__device__ int    g_cnt;
__device__ double g_lacc;

__device__ __forceinline__ uint32_t smem_u32(const void* p) {
    uint32_t a;
    asm("{ .reg .u64 t; cvta.to.shared.u64 t, %1; cvt.u32.u64 %0, t; }" : "=r"(a) : "l"(p));
    return a;
}
__device__ __forceinline__ void cvt2(float x, float y, uint32_t& h, uint32_t& l) {
    __nv_bfloat16 hx = __float2bfloat16(x), hy = __float2bfloat16(y);
    __nv_bfloat16 lx = __float2bfloat16(__fsub_rn(x, __bfloat162float(hx)));
    __nv_bfloat16 ly = __float2bfloat16(__fsub_rn(y, __bfloat162float(hy)));
    h = (uint32_t)__bfloat16_as_ushort(hx) | ((uint32_t)__bfloat16_as_ushort(hy) << 16);
    l = (uint32_t)__bfloat16_as_ushort(lx) | ((uint32_t)__bfloat16_as_ushort(ly) << 16);
}
__device__ __forceinline__ void mma_bf16(float& c0, float& c1, float& c2, float& c3,
                                         uint32_t a0, uint32_t a1, uint32_t a2, uint32_t a3,
                                         uint32_t b0, uint32_t b1) {
    asm volatile("mma.sync.aligned.m16n8k16.row.col.f32.bf16.bf16.f32 "
                 "{%0,%1,%2,%3}, {%4,%5,%6,%7}, {%8,%9}, {%0,%1,%2,%3};"
                 : "+f"(c0), "+f"(c1), "+f"(c2), "+f"(c3)
                 : "r"(a0), "r"(a1), "r"(a2), "r"(a3), "r"(b0), "r"(b1));
}
#define CP_ASYNC16(dst, src) \
    asm volatile("cp.async.cg.shared.global [%0], [%1], 16;" :: "r"(dst), "l"(src))
#define CP_COMMIT() asm volatile("cp.async.commit_group;" ::: "memory")
#define CP_WAIT0()  asm volatile("cp.async.wait_group 0;" ::: "memory")

// -------- k_prep: exact code norms + bf16 hi/lo fragment-layout codebook ---
__global__ void k_prep(const float* __restrict__ cb) {
    int k = blockIdx.x * blockDim.x + threadIdx.x;
    if (k == 0) { g_lacc = 0.0; g_cnt = 0; }
    if (k >= NCODE) return;
    const float* r = cb + (size_t)k * DIM;
    float s = 0.0f;
#pragma unroll
    for (int d = 0; d < DIM; ++d)
        s = __fadd_rn(s, __fmul_rn(r[d], r[d]));
    g_s2[k] = s;

    const int chunk = k >> 7, cc = k & 127, grp = cc >> 3, gg = cc & 7;
#pragma unroll
    for (int ks = 0; ks < 4; ++ks) {
        const int base = 16 * ks;
#pragma unroll
        for (int tg = 0; tg < 4; ++tg) {
            uint32_t bh0, bl0, bh1, bl1;
            cvt2(r[base + 2 * tg],     r[base + 2 * tg + 1],     bh0, bl0);
            cvt2(r[base + 8 + 2 * tg], r[base + 8 + 2 * tg + 1], bh1, bl1);
            g_bfrag[(size_t)(((chunk * 16 + grp) * 4 + ks) * 32 + gg * 4 + tg)] =
                make_uint4(bh0, bh1, bl0, bl1);
        }
    }
}

// -------- k_mma: 128 tokens/CTA, HMMA over 8 chunks of 128 codes -----------
__global__ void __launch_bounds__(256, 2) k_mma(const float* __restrict__ z) {
    extern __shared__ char smem[];
    uint4* bf  = (uint4*)smem;
    float* s2s = (float*)(smem + SM_S2);
    float* s1s = (float*)(smem + SM_S1);
    const uint32_t sbf = smem_u32(smem);
    const int tid = threadIdx.x;
    const int w = tid >> 5, lane = tid & 31;
    const int g = lane >> 2, tg = lane & 3;
    const int tok0 = blockIdx.x * 128;

    // stage chunk 0 into buf0
    {
        uint32_t dst = sbf + (uint32_t)tid * 16;
        const uint4* src = g_bfrag + tid;
#pragma unroll
        for (int i = 0; i < 8; ++i)
            CP_ASYNC16(dst + (uint32_t)i * 4096, src + i * 256);
        CP_COMMIT();
    }
    for (int i = tid; i < NCODE; i += 256) s2s[i] = g_s2[i];
    if (tid < 128) {
        const float4* zr = (const float4*)(z + (size_t)(tok0 + tid) * DIM);
        float s = 0.0f;
#pragma unroll
        for (int q = 0; q < 16; ++q) {
            float4 a = zr[q];
            s = __fadd_rn(s, __fmul_rn(a.x, a.x));
            s = __fadd_rn(s, __fmul_rn(a.y, a.y));
            s = __fadd_rn(s, __fmul_rn(a.z, a.z));
            s = __fadd_rn(s, __fmul_rn(a.w, a.w));
        }
        s1s[tid] = s;
    }

    // A fragments for this warp's 16 tokens (rows r0=g, r1=g+8 of warp tile)
    const int r0 = tok0 + w * 16 + g, r1 = r0 + 8;
    uint32_t ah[4][4], al[4][4];
#pragma unroll
    for (int ks = 0; ks < 4; ++ks) {
        const float* p0 = z + (size_t)r0 * DIM + ks * 16;
        const float* p1 = z + (size_t)r1 * DIM + ks * 16;
        float2 x0 = *(const float2*)(p0 + 2 * tg);
        float2 x1 = *(const float2*)(p1 + 2 * tg);
        float2 x2 = *(const float2*)(p0 + 8 + 2 * tg);
        float2 x3 = *(const float2*)(p1 + 8 + 2 * tg);
        cvt2(x0.x, x0.y, ah[ks][0], al[ks][0]);
        cvt2(x1.x, x1.y, ah[ks][1], al[ks][1]);
        cvt2(x2.x, x2.y, ah[ks][2], al[ks][2]);
        cvt2(x3.x, x3.y, ah[ks][3], al[ks][3]);
    }
    CP_WAIT0();
    __syncthreads();

    const float s1a = s1s[w * 16 + g];
    const float s1b = s1s[w * 16 + g + 8];

    float best0 = 3.402823466e38f, sec0 = 3.402823466e38f;
    float best1 = 3.402823466e38f, sec1 = 3.402823466e38f;
    int bi0 = 0, bi1 = 0;

#pragma unroll 1
    for (int c = 0; c < 8; ++c) {
        if (c < 7) {
            uint32_t dst = sbf + (uint32_t)(((c + 1) & 1) * 2048 + tid) * 16;
            const uint4* src = g_bfrag + (c + 1) * 2048 + tid;
#pragma unroll
            for (int i = 0; i < 8; ++i)
                CP_ASYNC16(dst + (uint32_t)i * 4096, src + i * 256);
            CP_COMMIT();
        }
        const uint4* bp = bf + (c & 1) * 2048 + lane;
        const float* s2c = s2s + c * 128;
#pragma unroll 1
        for (int nt = 0; nt < 16; nt += 2) {
            float p0 = 0.f, p1 = 0.f, p2 = 0.f, p3 = 0.f;
            float q0 = 0.f, q1 = 0.f, q2 = 0.f, q3 = 0.f;
#pragma unroll
            for (int ks = 0; ks < 4; ++ks) {
                uint4 B0 = bp[(nt * 4 + ks) * 32];
                uint4 B1 = bp[((nt + 1) * 4 + ks) * 32];
                mma_bf16(p0, p1, p2, p3, ah[ks][0], ah[ks][1], ah[ks][2], ah[ks][3], B0.x, B0.y);
                mma_bf16(q0, q1, q2, q3, ah[ks][0], ah[ks][1], ah[ks][2], ah[ks][3], B1.x, B1.y);
                mma_bf16(p0, p1, p2, p3, ah[ks][0], ah[ks][1], ah[ks][2], ah[ks][3], B0.z, B0.w);
                mma_bf16(q0, q1, q2, q3, ah[ks][0], ah[ks][1], ah[ks][2], ah[ks][3], B1.z, B1.w);
                mma_bf16(p0, p1, p2, p3, al[ks][0], al[ks][1], al[ks][2], al[ks][3], B0.x, B0.y);
                mma_bf16(q0, q1, q2, q3, al[ks][0], al[ks][1], al[ks][2], al[ks][3], B1.x, B1.y);
            }
#pragma unroll
            for (int h = 0; h < 2; ++h) {
                const int ntx = nt + h;
                const float e0 = h ? q0 : p0, e1 = h ? q1 : p1;
                const float e2 = h ? q2 : p2, e3 = h ? q3 : p3;
                const int j0 = c * 128 + ntx * 8 + 2 * tg;
                const float s2x = s2c[ntx * 8 + 2 * tg];
                const float s2y = s2c[ntx * 8 + 2 * tg + 1];
                // d = fl( fl(s1+s2) - fl(2e) ); (e+e) == fl(2e) exactly.
                float d00 = __fsub_rn(__fadd_rn(s1a, s2x), __fadd_rn(e0, e0));
                float d01 = __fsub_rn(__fadd_rn(s1a, s2y), __fadd_rn(e1, e1));
                float d10 = __fsub_rn(__fadd_rn(s1b, s2x), __fadd_rn(e2, e2));
                float d11 = __fsub_rn(__fadd_rn(s1b, s2y), __fadd_rn(e3, e3));
                if (d00 < best0) { sec0 = best0; best0 = d00; bi0 = j0; }
                else if (d00 < sec0) sec0 = d00;
                if (d01 < best0) { sec0 = best0; best0 = d01; bi0 = j0 + 1; }
                else if (d01 < sec0) sec0 = d01;
                if (d10 < best1) { sec1 = best1; best1 = d10; bi1 = j0; }
                else if (d10 < sec1) sec1 = d10;
                if (d11 < best1) { sec1 = best1; best1 = d11; bi1 = j0 + 1; }
                else if (d11 < sec1) sec1 = d11;
            }
        }
        CP_WAIT0();
        __syncthreads();
    }

    // merge (best, second, idx) across the 4 tg-lanes of each g
#pragma unroll
    for (int m = 1; m <= 2; m <<= 1) {
        float ob = __shfl_xor_sync(0xffffffffu, best0, m);
        float os = __shfl_xor_sync(0xffffffffu, sec0, m);
        int   oi = __shfl_xor_sync(0xffffffffu, bi0, m);
        if (ob < best0 || (ob == best0 && oi < bi0)) { sec0 = fminf(best0, os); best0 = ob; bi0 = oi; }
        else sec0 = fminf(sec0, ob);
        ob = __shfl_xor_sync(0xffffffffu, best1, m);
        os = __shfl_xor_sync(0xffffffffu, sec1, m);
        oi = __shfl_xor_sync(0xffffffffu, bi1, m);
        if (ob < best1 || (ob == best1 && oi < bi1)) { sec1 = fminf(best1, os); best1 = ob; bi1 = oi; }
        else sec1 = fminf(sec1, ob);
    }
    if (tg == 0) {
        g_idx[r0] = bi0;
        g_idx[r1] = bi1;
        if (__fsub_rn(sec0, best0) <= THRESH) { int p = atomicAdd(&g_cnt, 1); g_list[p] = r0; }
        if (__fsub_rn(sec1, best1) <= THRESH) { int p = atomicAdd(&g_cnt, 1); g_list[p] = r1; }
    }
}

// -------- k_rescue: exact rescore of flagged tokens (R5 rounding chain) ----
__global__ void __launch_bounds__(128) k_rescue(const float* __restrict__ z,
                                                const float* __restrict__ cb) {
    __shared__ float cbs[64 * 64];
    __shared__ float s2s[64];
    __shared__ float zs[16][64];
    __shared__ float s1s[16];
    __shared__ int   toks[16];
    const int tid = threadIdx.x;
    const int cnt = g_cnt;

    for (int base = blockIdx.x * 16; base < cnt; base += gridDim.x * 16) {
        int nb = cnt - base; if (nb > 16) nb = 16;
        __syncthreads();
        if (tid < 16) toks[tid] = g_list[base + (tid < nb ? tid : 0)];
        __syncthreads();
        for (int i = tid; i < nb * 64; i += 128) {
            int t = i >> 6, d = i & 63;
            zs[t][d] = z[(size_t)toks[t] * 64 + d];
        }
        __syncthreads();
        if (tid < nb) {
            float s = 0.0f;
#pragma unroll
            for (int d = 0; d < 64; d++)
                s = __fadd_rn(s, __fmul_rn(zs[tid][d], zs[tid][d]));
            s1s[tid] = s;
        }
        float best = 3.402823466e38f;
        int bi = NCODE;
        const int tb = tid >> 3, sl = tid & 7;
        for (int c0 = 0; c0 < NCODE; c0 += 64) {
            __syncthreads();
            for (int i = tid; i < 64 * 64; i += 128) cbs[i] = cb[c0 * 64 + i];
            if (tid < 64) s2s[tid] = g_s2[c0 + tid];
            __syncthreads();
            if (tb < nb) {
                for (int kk = sl; kk < 64; kk += 16) {
                    const float* cr0 = &cbs[kk * 64];
                    const float* cr1 = &cbs[(kk + 8) * 64];
                    float e0 = 0.0f, e1 = 0.0f;   // two independent exact chains
#pragma unroll
                    for (int d = 0; d < 64; d++) {
                        e0 = __fmaf_rn(zs[tb][d], cr0[d], e0);
                        e1 = __fmaf_rn(zs[tb][d], cr1[d], e1);
                    }
                    float d0 = __fsub_rn(__fadd_rn(s1s[tb], s2s[kk]),     __fmul_rn(2.0f, e0));
                    float d1 = __fsub_rn(__fadd_rn(s1s[tb], s2s[kk + 8]), __fmul_rn(2.0f, e1));
                    if (d0 < best) { best = d0; bi = c0 + kk; }
                    if (d1 < best) { best = d1; bi = c0 + kk + 8; }
                }
            }
        }
#pragma unroll
        for (int m = 4; m; m >>= 1) {
            float ob = __shfl_xor_sync(0xffffffffu, best, m);
            int   oi = __shfl_xor_sync(0xffffffffu, bi, m);
            if (ob < best || (ob == best && oi < bi)) { best = ob; bi = oi; }
        }
        if (sl == 0 && tb < nb) g_idx[toks[tb]] = bi;
    }
}

// -------- k_gather: z_q_st, indices, loss partials --------------------------
__global__ void __launch_bounds__(256) k_gather(const float* __restrict__ z,
                                                const float* __restrict__ cb,
                                                float* __restrict__ out) {
    __shared__ double lred[256];
    const int j = blockIdx.x * 256 + threadIdx.x;   // [0, N_TOK*16)
    const int tok = j >> 4, q = j & 15;
    const int idx = g_idx[tok];
    float4 cv = ((const float4*)cb)[idx * 16 + q];
    float4 zv = ((const float4*)z)[j];
    float4 w;
    double ls = 0.0;
    float df;
    df = __fsub_rn(cv.x, zv.x); w.x = __fadd_rn(zv.x, df); ls += (double)__fmul_rn(df, df);
    df = __fsub_rn(cv.y, zv.y); w.y = __fadd_rn(zv.y, df); ls += (double)__fmul_rn(df, df);
    df = __fsub_rn(cv.z, zv.z); w.z = __fadd_rn(zv.z, df); ls += (double)__fmul_rn(df, df);
    df = __fsub_rn(cv.w, zv.w); w.w = __fadd_rn(zv.w, df); ls += (double)__fmul_rn(df, df);
    ((float4*)out)[j] = w;
    if (q == 0) out[OUT_IDX + tok] = (float)idx;
    lred[threadIdx.x] = ls;
    __syncthreads();
#pragma unroll
    for (int s = 128; s; s >>= 1) {
        if (threadIdx.x < s) lred[threadIdx.x] += lred[threadIdx.x + s];
        __syncthreads();
    }
    if (threadIdx.x == 0) atomicAdd(&g_lacc, lred[0]);
}

__global__ void k_fin(float* __restrict__ out) {
    double m = g_lacc / (double)((double)N_TOK * (double)DIM);
    float mf = (float)m;
    out[OUT_LOSS] = __fadd_rn(mf, mf);
}

extern "C" void kernel_launch(void* const* d_in, const int* in_sizes, int n_in,
                              void* d_out, int out_size) {
    const float* z = (const float*)d_in[0];
    const float* cb = (const float*)d_in[1];
    float* out = (float*)d_out;

    static bool attr_done = false;
    if (!attr_done) {
        cudaFuncSetAttribute(k_mma, cudaFuncAttributeMaxDynamicSharedMemorySize, SM_TOTAL);
        attr_done = true;
    }
    k_prep<<<8, 128>>>(cb);
    k_mma<<<N_TOK / 128, 256, SM_TOTAL>>>(z);
    k_rescue<<<148, 128>>>(z, cb);
    k_gather<<<N_TOK * 16 / 256, 256>>>(z, cb, out);
    k_fin<<<1, 1>>>(out);
}